// round 10
// baseline (speedup 1.0000x reference)
#include <cuda_runtime.h>
#include <cuda_bf16.h>

#define SL 1024
#define NE 4
#define ND 128
#define NBATCH 4
#define KA (SL*NE)

typedef unsigned long long u64;
typedef unsigned int u32;

// ---- scratch (no allocs allowed) ----
__device__ __align__(128) float g_pi[(size_t)NBATCH*KA*ND];
__device__ __align__(128) float g_po[(size_t)NBATCH*KA*ND];
__device__ __align__(128) float g_ni[(size_t)NBATCH*SL*ND];
__device__ __align__(128) float g_no[(size_t)NBATCH*SL*ND];
__device__ __align__(128) float g_st[(size_t)NBATCH*SL*ND];

// ---- packed f32x2 helpers ----
__device__ __forceinline__ u64 pk2(float a, float b){
    u64 r; asm("mov.b64 %0,{%1,%2};":"=l"(r):"r"(__float_as_uint(a)),"r"(__float_as_uint(b))); return r;
}
__device__ __forceinline__ void upk2(u64 v, float&a, float&b){
    u32 lo,hi; asm("mov.b64 {%0,%1},%2;":"=r"(lo),"=r"(hi):"l"(v));
    a=__uint_as_float(lo); b=__uint_as_float(hi);
}
__device__ __forceinline__ void fma2(u64&d, u64 a, u64 b){
    asm("fma.rn.f32x2 %0,%1,%2,%0;":"+l"(d):"l"(a),"l"(b));
}
__device__ __forceinline__ float sigm(float v){ return 1.f/(1.f+__expf(-v)); }

__device__ __forceinline__ u32 smem_u32(const void* p){
    u32 a; asm("{ .reg .u64 t; cvta.to.shared.u64 t,%1; cvt.u32.u64 %0,t; }":"=r"(a):"l"(p));
    return a;
}
__device__ __forceinline__ void cpa16(u32 dst, const void* src){
    asm volatile("cp.async.cg.shared.global [%0],[%1],16;"::"r"(dst),"l"(src));
}
__device__ __forceinline__ void cpa_commit(){ asm volatile("cp.async.commit_group;"); }
__device__ __forceinline__ void cpa_wait0(){ asm volatile("cp.async.wait_group 0;"); }
__device__ __forceinline__ void cpa_wait1(){ asm volatile("cp.async.wait_group 1;"); }
__device__ __forceinline__ void cpa_wait2(){ asm volatile("cp.async.wait_group 2;"); }

struct Smem { u64 A2[16][64]; float Bs[16][128]; };          // 16 KB
struct GSmem { Smem g; float ro[64][ND]; };                   // 48 KB

// ---- round-2 verified 64x128 FFMA2 GEMM core (proj/gru only) ----
template<int NT, bool SEG3>
__device__ __forceinline__ void gemm64(
    const float* a0, const float* a1, const float* a2, int lda,
    const float* __restrict__ Bmat, u64 (&acc)[4][4], Smem& sm)
{
    const int tid=threadIdx.x;
    const int r0=(tid>>4)*4, c0=(tid&15)*8;
    const int arow=tid>>2, ac=(tid&3)*4;
    const int bw=tid>>5, bc=(tid&31)*4;
    float4 ra,rb0,rb1;
    ra  = *(const float4*)(a0 + (size_t)arow*lda + ac);
    rb0 = *(const float4*)(Bmat + bw*ND + bc);
    rb1 = *(const float4*)(Bmat + (bw+8)*ND + bc);
#pragma unroll 1
    for (int kt=0; kt<NT; ++kt){
        sm.A2[ac+0][arow]=pk2(ra.x,ra.x); sm.A2[ac+1][arow]=pk2(ra.y,ra.y);
        sm.A2[ac+2][arow]=pk2(ra.z,ra.z); sm.A2[ac+3][arow]=pk2(ra.w,ra.w);
        *(float4*)&sm.Bs[bw][bc]=rb0; *(float4*)&sm.Bs[bw+8][bc]=rb1;
        __syncthreads();
        if (kt+1<NT){
            const int kn=kt+1; const float* ap; int off;
            if (SEG3){ ap=(kn<8)?a0:((kn<16)?a1:a2); off=(kn&7)*16; }
            else     { ap=a0; off=kn*16; }
            ra = *(const float4*)(ap + (size_t)arow*lda + off + ac);
            const float* bp = Bmat + (size_t)kn*16*ND;
            rb0 = *(const float4*)(bp + bw*ND + bc);
            rb1 = *(const float4*)(bp + (bw+8)*ND + bc);
        }
#pragma unroll
        for (int kk=0;kk<16;++kk){
            u64 a0v=sm.A2[kk][r0],a1v=sm.A2[kk][r0+1],a2v=sm.A2[kk][r0+2],a3v=sm.A2[kk][r0+3];
            ulonglong2 b01=*(const ulonglong2*)&sm.Bs[kk][c0];
            ulonglong2 b23=*(const ulonglong2*)&sm.Bs[kk][c0+4];
            fma2(acc[0][0],a0v,b01.x); fma2(acc[0][1],a0v,b01.y); fma2(acc[0][2],a0v,b23.x); fma2(acc[0][3],a0v,b23.y);
            fma2(acc[1][0],a1v,b01.x); fma2(acc[1][1],a1v,b01.y); fma2(acc[1][2],a1v,b23.x); fma2(acc[1][3],a1v,b23.y);
            fma2(acc[2][0],a2v,b01.x); fma2(acc[2][1],a2v,b01.y); fma2(acc[2][2],a2v,b23.x); fma2(acc[2][3],a2v,b23.y);
            fma2(acc[3][0],a3v,b01.x); fma2(acc[3][1],a3v,b01.y); fma2(acc[3][2],a3v,b23.x); fma2(acc[3][3],a3v,b23.y);
        }
        __syncthreads();
    }
}
#define ZERO_ACC(acc) { _Pragma("unroll") for(int i=0;i<4;++i){ _Pragma("unroll") for(int j=0;j<4;++j) acc[i][j]=0ull; } }

// ---- kernel 1: per-edge projections (round-2 verbatim; PASSED) ----
__global__ void __launch_bounds__(256) proj_kernel(
    const float* __restrict__ x,
    const float* __restrict__ W_ein, const float* __restrict__ b_ein,
    const float* __restrict__ W_eout, const float* __restrict__ b_eout, int use_x)
{
    __shared__ Smem sm;
    const int stile=blockIdx.x, e=blockIdx.y>>1, dir=blockIdx.y&1, b=blockIdx.z;
    const float* src = (use_x? x : (const float*)g_st) + (size_t)b*SL*ND + (size_t)stile*64*ND;
    const float* W   = (dir? W_eout : W_ein) + (size_t)e*ND*ND;
    const float* bias= (dir? b_eout : b_ein) + e*ND;
    float* dst = (dir? g_po : g_pi) + (size_t)b*KA*ND;

    u64 acc[4][4]; ZERO_ACC(acc);
    gemm64<8,false>(src, src, src, ND, W, acc, sm);

    const int tid=threadIdx.x, r0=(tid>>4)*4, c0=(tid&15)*8;
#pragma unroll
    for (int i=0;i<4;++i){
        const int s = stile*64 + r0 + i;
        float* drow = dst + ((size_t)s*NE + e)*ND;
        float v0,v1,v2,v3;
        upk2(acc[i][0],v0,v1); upk2(acc[i][1],v2,v3);
        *(float4*)(drow+c0)   = make_float4(v0+bias[c0],v1+bias[c0+1],v2+bias[c0+2],v3+bias[c0+3]);
        upk2(acc[i][2],v0,v1); upk2(acc[i][3],v2,v3);
        *(float4*)(drow+c0+4) = make_float4(v0+bias[c0+4],v1+bias[c0+5],v2+bias[c0+6],v3+bias[c0+7]);
    }
}

// ---- kernel 2: fp32 aggregation, cp.async pipelined (new core) ----
// smem: B ring 4 x (16x128 f32) = 32KB ; A dup 2 x (16x64 u64) = 16KB ; total 48KB static
__global__ void __launch_bounds__(256) agg_kernel(
    const float* __restrict__ A_in, const float* __restrict__ A_out)
{
    __shared__ __align__(16) float Bs[4][16][128];
    __shared__ __align__(16) u64  As[2][16][64];

    const int tid=threadIdx.x;
    const int mtile=blockIdx.x, dir=blockIdx.y, b=blockIdx.z;
    const float* Arow = (dir? A_out : A_in) + (size_t)b*SL*KA + (size_t)mtile*64*KA;
    const float* Prow = (dir? g_po : g_pi) + (size_t)b*KA*ND;

    const int arow=tid>>2, ac=(tid&3)*4;          // A loader: 64 rows x 16 cols
    const u32 bbase = smem_u32(&Bs[0][0][0]);

    auto issueB = [&](int t){
        const u32 slot = bbase + (u32)(t&3)*8192;
#pragma unroll
        for (int j=0;j<2;++j){
            const int id=tid*2+j, r=id>>5, cchunk=id&31;
            cpa16(slot + r*512 + cchunk*16, Prow + (size_t)(t*16+r)*ND + cchunk*4);
        }
        cpa_commit();
    };

    // prologue
    float4 ra = *(const float4*)(Arow + (size_t)arow*KA + ac);       // A(0)
    issueB(0); issueB(1); issueB(2);
    As[0][ac+0][arow]=pk2(ra.x,ra.x); As[0][ac+1][arow]=pk2(ra.y,ra.y);
    As[0][ac+2][arow]=pk2(ra.z,ra.z); As[0][ac+3][arow]=pk2(ra.w,ra.w);
    ra = *(const float4*)(Arow + (size_t)arow*KA + 16 + ac);         // A(1)
    __syncthreads();

    const int r0=(tid>>4)*4, c0=(tid&15)*8;
    u64 acc[4][4]; ZERO_ACC(acc);

#pragma unroll 1
    for (int t=0; t<256; ++t){
        if (t<254) cpa_wait2(); else if (t==254) cpa_wait1(); else cpa_wait0();
        __syncthreads();                       // B(t) + As[t&1] visible
        if (t+3<256) issueB(t+3);              // into slot (t+3)&3 == (t-1)&3 (drained)
        // stage A(t+1) into the other buffer; prefetch A(t+2)
        if (t+1<256){
            const int nb=(t+1)&1;
            As[nb][ac+0][arow]=pk2(ra.x,ra.x); As[nb][ac+1][arow]=pk2(ra.y,ra.y);
            As[nb][ac+2][arow]=pk2(ra.z,ra.z); As[nb][ac+3][arow]=pk2(ra.w,ra.w);
        }
        if (t+2<256)
            ra = *(const float4*)(Arow + (size_t)arow*KA + (t+2)*16 + ac);
        const int cb=t&1, bs=t&3;
#pragma unroll
        for (int kk=0;kk<16;++kk){
            u64 a0v=As[cb][kk][r0],a1v=As[cb][kk][r0+1],a2v=As[cb][kk][r0+2],a3v=As[cb][kk][r0+3];
            ulonglong2 b01=*(const ulonglong2*)&Bs[bs][kk][c0];
            ulonglong2 b23=*(const ulonglong2*)&Bs[bs][kk][c0+4];
            fma2(acc[0][0],a0v,b01.x); fma2(acc[0][1],a0v,b01.y); fma2(acc[0][2],a0v,b23.x); fma2(acc[0][3],a0v,b23.y);
            fma2(acc[1][0],a1v,b01.x); fma2(acc[1][1],a1v,b01.y); fma2(acc[1][2],a1v,b23.x); fma2(acc[1][3],a1v,b23.y);
            fma2(acc[2][0],a2v,b01.x); fma2(acc[2][1],a2v,b01.y); fma2(acc[2][2],a2v,b23.x); fma2(acc[2][3],a2v,b23.y);
            fma2(acc[3][0],a3v,b01.x); fma2(acc[3][1],a3v,b01.y); fma2(acc[3][2],a3v,b23.x); fma2(acc[3][3],a3v,b23.y);
        }
        __syncthreads();                       // readers done before slot reuse next iters
    }

    float* dst = (dir? g_no : g_ni) + (size_t)b*SL*ND + (size_t)mtile*64*ND;
#pragma unroll
    for (int i=0;i<4;++i){
        float* drow = dst + (size_t)(r0+i)*ND;
        float v0,v1,v2,v3;
        upk2(acc[i][0],v0,v1); upk2(acc[i][1],v2,v3);
        *(float4*)(drow+c0)   = make_float4(v0,v1,v2,v3);
        upk2(acc[i][2],v0,v1); upk2(acc[i][3],v2,v3);
        *(float4*)(drow+c0+4) = make_float4(v0,v1,v2,v3);
    }
}

// ---- kernel 3: fused GRU update (round-2 verbatim; PASSED) ----
__global__ void __launch_bounds__(256) gru_kernel(
    const float* __restrict__ x,
    const float* __restrict__ W_r, const float* __restrict__ b_r,
    const float* __restrict__ W_z, const float* __restrict__ b_z,
    const float* __restrict__ W_h, const float* __restrict__ b_h,
    float* __restrict__ dout, int use_x, int is_final)
{
    __shared__ GSmem s;
    const int stile=blockIdx.x, b=blockIdx.z;
    const size_t base=(size_t)b*SL*ND + (size_t)stile*64*ND;
    const float* ni=g_ni+base; const float* no=g_no+base;
    const float* st=(use_x? x : (const float*)g_st)+base;
    const int tid=threadIdx.x, r0=(tid>>4)*4, c0=(tid&15)*8;

    u64 acc[4][4];
    ZERO_ACC(acc);
    gemm64<24,true>(ni,no,st,ND,W_r,acc,s.g);

    float stv[4][8];
#pragma unroll
    for (int i=0;i<4;++i){
        float4 p0=*(const float4*)(st+(size_t)(r0+i)*ND+c0);
        float4 p1=*(const float4*)(st+(size_t)(r0+i)*ND+c0+4);
        stv[i][0]=p0.x; stv[i][1]=p0.y; stv[i][2]=p0.z; stv[i][3]=p0.w;
        stv[i][4]=p1.x; stv[i][5]=p1.y; stv[i][6]=p1.z; stv[i][7]=p1.w;
    }
#pragma unroll
    for (int i=0;i<4;++i)
#pragma unroll
        for (int j=0;j<4;++j){
            float v0,v1; upk2(acc[i][j],v0,v1);
            const int c=c0+2*j;
            s.ro[r0+i][c]   = sigm(v0+b_r[c])  *stv[i][2*j];
            s.ro[r0+i][c+1] = sigm(v1+b_r[c+1])*stv[i][2*j+1];
        }
    __syncthreads();

    ZERO_ACC(acc);
    gemm64<24,true>(ni,no,st,ND,W_z,acc,s.g);
    float zv[4][8];
#pragma unroll
    for (int i=0;i<4;++i)
#pragma unroll
        for (int j=0;j<4;++j){
            float v0,v1; upk2(acc[i][j],v0,v1);
            zv[i][2*j]  =sigm(v0+b_z[c0+2*j]);
            zv[i][2*j+1]=sigm(v1+b_z[c0+2*j+1]);
        }

    ZERO_ACC(acc);
    gemm64<24,true>(ni,no,(const float*)s.ro,ND,W_h,acc,s.g);

    float* ost = g_st + base;
    float* od  = dout + base;
#pragma unroll
    for (int i=0;i<4;++i){
        float o[8];
#pragma unroll
        for (int j=0;j<4;++j){
            float v0,v1; upk2(acc[i][j],v0,v1);
            float h0=tanhf(v0+b_h[c0+2*j]), h1=tanhf(v1+b_h[c0+2*j+1]);
            o[2*j]  =(1.f-zv[i][2*j])  *stv[i][2*j]  + zv[i][2*j]  *h0;
            o[2*j+1]=(1.f-zv[i][2*j+1])*stv[i][2*j+1] + zv[i][2*j+1]*h1;
        }
        *(float4*)(ost+(size_t)(r0+i)*ND+c0)   = make_float4(o[0],o[1],o[2],o[3]);
        *(float4*)(ost+(size_t)(r0+i)*ND+c0+4) = make_float4(o[4],o[5],o[6],o[7]);
        if (is_final){
            *(float4*)(od+(size_t)(r0+i)*ND+c0)   = make_float4(o[0],o[1],o[2],o[3]);
            *(float4*)(od+(size_t)(r0+i)*ND+c0+4) = make_float4(o[4],o[5],o[6],o[7]);
        }
    }
}

extern "C" void kernel_launch(void* const* d_in, const int* in_sizes, int n_in,
                              void* d_out, int out_size)
{
    const float* x      = (const float*)d_in[0];
    const float* A_in   = (const float*)d_in[1];
    const float* A_out  = (const float*)d_in[2];
    const float* W_ein  = (const float*)d_in[3];
    const float* b_ein  = (const float*)d_in[4];
    const float* W_eout = (const float*)d_in[5];
    const float* b_eout = (const float*)d_in[6];
    const float* W_r    = (const float*)d_in[7];
    const float* b_r    = (const float*)d_in[8];
    const float* W_z    = (const float*)d_in[9];
    const float* b_z    = (const float*)d_in[10];
    const float* W_h    = (const float*)d_in[11];
    const float* b_h    = (const float*)d_in[12];
    float* out = (float*)d_out;

    for (int step=0; step<5; ++step){
        const int use_x = (step==0), fin = (step==4);
        proj_kernel<<<dim3(16,8,4),256>>>(x, W_ein,b_ein,W_eout,b_eout, use_x);
        agg_kernel <<<dim3(16,2,4),256>>>(A_in, A_out);
        gru_kernel <<<dim3(16,1,4),256>>>(x, W_r,b_r,W_z,b_z,W_h,b_h, out, use_x, fin);
    }
}

// round 11
// speedup vs baseline: 1.4999x; 1.4999x over previous
#include <cuda_runtime.h>
#include <cuda_bf16.h>

#define SL 1024
#define NE 4
#define ND 128
#define NBATCH 4
#define KA (SL*NE)

typedef unsigned long long u64;
typedef unsigned int u32;

// ---- scratch (no allocs allowed) ----
__device__ __align__(128) float g_pi[(size_t)NBATCH*KA*ND];
__device__ __align__(128) float g_po[(size_t)NBATCH*KA*ND];
__device__ __align__(128) float g_ni[(size_t)NBATCH*SL*ND];
__device__ __align__(128) float g_no[(size_t)NBATCH*SL*ND];
__device__ __align__(128) float g_st[(size_t)NBATCH*SL*ND];

// ---- packed f32x2 helpers ----
__device__ __forceinline__ u64 pk2(float a, float b){
    u64 r; asm("mov.b64 %0,{%1,%2};":"=l"(r):"r"(__float_as_uint(a)),"r"(__float_as_uint(b))); return r;
}
__device__ __forceinline__ void upk2(u64 v, float&a, float&b){
    u32 lo,hi; asm("mov.b64 {%0,%1},%2;":"=r"(lo),"=r"(hi):"l"(v));
    a=__uint_as_float(lo); b=__uint_as_float(hi);
}
__device__ __forceinline__ void fma2(u64&d, u64 a, u64 b){
    asm("fma.rn.f32x2 %0,%1,%2,%0;":"+l"(d):"l"(a),"l"(b));
}
__device__ __forceinline__ float sigm(float v){ return 1.f/(1.f+__expf(-v)); }

__device__ __forceinline__ u32 smem_u32(const void* p){
    u32 a; asm("{ .reg .u64 t; cvta.to.shared.u64 t,%1; cvt.u32.u64 %0,t; }":"=r"(a):"l"(p));
    return a;
}
__device__ __forceinline__ void cpa16(u32 dst, const void* src){
    asm volatile("cp.async.cg.shared.global [%0],[%1],16;"::"r"(dst),"l"(src));
}
__device__ __forceinline__ void cpa_commit(){ asm volatile("cp.async.commit_group;"); }
__device__ __forceinline__ void cpa_wait0(){ asm volatile("cp.async.wait_group 0;"); }
__device__ __forceinline__ void cpa_wait1(){ asm volatile("cp.async.wait_group 1;"); }
__device__ __forceinline__ void cpa_wait2(){ asm volatile("cp.async.wait_group 2;"); }

struct Smem { u64 A2[16][64]; float Bs[16][128]; };          // 16 KB
struct GSmem { Smem g; float ro[64][ND]; };                   // 48 KB

// ---- round-2 verified 64x128 FFMA2 GEMM core (proj/gru only; untouched) ----
template<int NT, bool SEG3>
__device__ __forceinline__ void gemm64(
    const float* a0, const float* a1, const float* a2, int lda,
    const float* __restrict__ Bmat, u64 (&acc)[4][4], Smem& sm)
{
    const int tid=threadIdx.x;
    const int r0=(tid>>4)*4, c0=(tid&15)*8;
    const int arow=tid>>2, ac=(tid&3)*4;
    const int bw=tid>>5, bc=(tid&31)*4;
    float4 ra,rb0,rb1;
    ra  = *(const float4*)(a0 + (size_t)arow*lda + ac);
    rb0 = *(const float4*)(Bmat + bw*ND + bc);
    rb1 = *(const float4*)(Bmat + (bw+8)*ND + bc);
#pragma unroll 1
    for (int kt=0; kt<NT; ++kt){
        sm.A2[ac+0][arow]=pk2(ra.x,ra.x); sm.A2[ac+1][arow]=pk2(ra.y,ra.y);
        sm.A2[ac+2][arow]=pk2(ra.z,ra.z); sm.A2[ac+3][arow]=pk2(ra.w,ra.w);
        *(float4*)&sm.Bs[bw][bc]=rb0; *(float4*)&sm.Bs[bw+8][bc]=rb1;
        __syncthreads();
        if (kt+1<NT){
            const int kn=kt+1; const float* ap; int off;
            if (SEG3){ ap=(kn<8)?a0:((kn<16)?a1:a2); off=(kn&7)*16; }
            else     { ap=a0; off=kn*16; }
            ra = *(const float4*)(ap + (size_t)arow*lda + off + ac);
            const float* bp = Bmat + (size_t)kn*16*ND;
            rb0 = *(const float4*)(bp + bw*ND + bc);
            rb1 = *(const float4*)(bp + (bw+8)*ND + bc);
        }
#pragma unroll
        for (int kk=0;kk<16;++kk){
            u64 a0v=sm.A2[kk][r0],a1v=sm.A2[kk][r0+1],a2v=sm.A2[kk][r0+2],a3v=sm.A2[kk][r0+3];
            ulonglong2 b01=*(const ulonglong2*)&sm.Bs[kk][c0];
            ulonglong2 b23=*(const ulonglong2*)&sm.Bs[kk][c0+4];
            fma2(acc[0][0],a0v,b01.x); fma2(acc[0][1],a0v,b01.y); fma2(acc[0][2],a0v,b23.x); fma2(acc[0][3],a0v,b23.y);
            fma2(acc[1][0],a1v,b01.x); fma2(acc[1][1],a1v,b01.y); fma2(acc[1][2],a1v,b23.x); fma2(acc[1][3],a1v,b23.y);
            fma2(acc[2][0],a2v,b01.x); fma2(acc[2][1],a2v,b01.y); fma2(acc[2][2],a2v,b23.x); fma2(acc[2][3],a2v,b23.y);
            fma2(acc[3][0],a3v,b01.x); fma2(acc[3][1],a3v,b01.y); fma2(acc[3][2],a3v,b23.x); fma2(acc[3][3],a3v,b23.y);
        }
        __syncthreads();
    }
}
#define ZERO_ACC(acc) { _Pragma("unroll") for(int i=0;i<4;++i){ _Pragma("unroll") for(int j=0;j<4;++j) acc[i][j]=0ull; } }

// ---- kernel 1: per-edge projections (verified; untouched) ----
__global__ void __launch_bounds__(256) proj_kernel(
    const float* __restrict__ x,
    const float* __restrict__ W_ein, const float* __restrict__ b_ein,
    const float* __restrict__ W_eout, const float* __restrict__ b_eout, int use_x)
{
    __shared__ Smem sm;
    const int stile=blockIdx.x, e=blockIdx.y>>1, dir=blockIdx.y&1, b=blockIdx.z;
    const float* src = (use_x? x : (const float*)g_st) + (size_t)b*SL*ND + (size_t)stile*64*ND;
    const float* W   = (dir? W_eout : W_ein) + (size_t)e*ND*ND;
    const float* bias= (dir? b_eout : b_ein) + e*ND;
    float* dst = (dir? g_po : g_pi) + (size_t)b*KA*ND;

    u64 acc[4][4]; ZERO_ACC(acc);
    gemm64<8,false>(src, src, src, ND, W, acc, sm);

    const int tid=threadIdx.x, r0=(tid>>4)*4, c0=(tid&15)*8;
#pragma unroll
    for (int i=0;i<4;++i){
        const int s = stile*64 + r0 + i;
        float* drow = dst + ((size_t)s*NE + e)*ND;
        float v0,v1,v2,v3;
        upk2(acc[i][0],v0,v1); upk2(acc[i][1],v2,v3);
        *(float4*)(drow+c0)   = make_float4(v0+bias[c0],v1+bias[c0+1],v2+bias[c0+2],v3+bias[c0+3]);
        upk2(acc[i][2],v0,v1); upk2(acc[i][3],v2,v3);
        *(float4*)(drow+c0+4) = make_float4(v0+bias[c0+4],v1+bias[c0+5],v2+bias[c0+6],v3+bias[c0+7]);
    }
}

// ---- kernel 2: fp32 aggregation — 8x8 microtile, conflict-free LDS ----
// 128 threads/CTA, tile M=64 x N=128, 256 K-tiles of 16.
// smem: B ring 4 x (16x128 f32) = 32KB ; A raw 2 x (16x64 f32) = 8KB
__global__ void __launch_bounds__(128,2) agg_kernel(
    const float* __restrict__ A_in, const float* __restrict__ A_out)
{
    __shared__ __align__(16) float Bs[4][16][128];
    __shared__ __align__(16) float As[2][16][64];

    const int tid=threadIdx.x;
    const int mtile=blockIdx.x, dir=blockIdx.y, b=blockIdx.z;
    const float* Arow = (dir? A_out : A_in) + (size_t)b*SL*KA + (size_t)mtile*64*KA;
    const float* Prow = (dir? g_po : g_pi) + (size_t)b*KA*ND;

    const u32 bbase = smem_u32(&Bs[0][0][0]);
    auto issueB = [&](int t){
        const u32 slot = bbase + (u32)(t&3)*8192;
#pragma unroll
        for (int j=0;j<4;++j){
            const int id=tid+j*128, r=id>>5, c=id&31;
            cpa16(slot + r*512 + c*16, Prow + (size_t)(t*16+r)*ND + c*4);
        }
        cpa_commit();
    };

    // A loader role: row = tid&63, k-offset = (tid>>6)*8 (bank-conflict-free STS)
    const int ar = tid&63, akc = (tid>>6)*8;
    auto stsA = [&](int buf, const float4& p0, const float4& p1){
        As[buf][akc+0][ar]=p0.x; As[buf][akc+1][ar]=p0.y;
        As[buf][akc+2][ar]=p0.z; As[buf][akc+3][ar]=p0.w;
        As[buf][akc+4][ar]=p1.x; As[buf][akc+5][ar]=p1.y;
        As[buf][akc+6][ar]=p1.z; As[buf][akc+7][ar]=p1.w;
    };

    // prologue
    float4 ra0 = *(const float4*)(Arow + (size_t)ar*KA + akc);
    float4 ra1 = *(const float4*)(Arow + (size_t)ar*KA + akc + 4);
    issueB(0); issueB(1); issueB(2);
    stsA(0, ra0, ra1);
    ra0 = *(const float4*)(Arow + (size_t)ar*KA + 16 + akc);
    ra1 = *(const float4*)(Arow + (size_t)ar*KA + 16 + akc + 4);

    // compute roles: 8 rows x 8 cols per thread
    const int rg = tid>>4;                 // 0..7 -> rows rg*8..rg*8+7
    const int cA = (tid&15)*4, cB = 64 + cA;
    u64 acc[8][4];
#pragma unroll
    for (int i=0;i<8;++i)
#pragma unroll
        for (int j=0;j<4;++j) acc[i][j]=0ull;

#pragma unroll 1
    for (int t=0; t<256; ++t){
        if (t<254) cpa_wait2(); else if (t==254) cpa_wait1(); else cpa_wait0();
        __syncthreads();                       // B(t) + A(t) visible; slot (t+3)&3 drained
        if (t+3<256) issueB(t+3);
        if (t+1<256) stsA((t+1)&1, ra0, ra1);
        if (t+2<256){
            ra0 = *(const float4*)(Arow + (size_t)ar*KA + (t+2)*16 + akc);
            ra1 = *(const float4*)(Arow + (size_t)ar*KA + (t+2)*16 + akc + 4);
        }
        const int ab=t&1, bs=t&3;
#pragma unroll
        for (int kk=0;kk<16;++kk){
            float4 pa0 = *(const float4*)&As[ab][kk][rg*8];
            float4 pa1 = *(const float4*)&As[ab][kk][rg*8+4];
            ulonglong2 bA = *(const ulonglong2*)&Bs[bs][kk][cA];
            ulonglong2 bB = *(const ulonglong2*)&Bs[bs][kk][cB];
            u64 a0=pk2(pa0.x,pa0.x), a1=pk2(pa0.y,pa0.y), a2=pk2(pa0.z,pa0.z), a3=pk2(pa0.w,pa0.w);
            u64 a4=pk2(pa1.x,pa1.x), a5=pk2(pa1.y,pa1.y), a6=pk2(pa1.z,pa1.z), a7=pk2(pa1.w,pa1.w);
            fma2(acc[0][0],a0,bA.x); fma2(acc[0][1],a0,bA.y); fma2(acc[0][2],a0,bB.x); fma2(acc[0][3],a0,bB.y);
            fma2(acc[1][0],a1,bA.x); fma2(acc[1][1],a1,bA.y); fma2(acc[1][2],a1,bB.x); fma2(acc[1][3],a1,bB.y);
            fma2(acc[2][0],a2,bA.x); fma2(acc[2][1],a2,bA.y); fma2(acc[2][2],a2,bB.x); fma2(acc[2][3],a2,bB.y);
            fma2(acc[3][0],a3,bA.x); fma2(acc[3][1],a3,bA.y); fma2(acc[3][2],a3,bB.x); fma2(acc[3][3],a3,bB.y);
            fma2(acc[4][0],a4,bA.x); fma2(acc[4][1],a4,bA.y); fma2(acc[4][2],a4,bB.x); fma2(acc[4][3],a4,bB.y);
            fma2(acc[5][0],a5,bA.x); fma2(acc[5][1],a5,bA.y); fma2(acc[5][2],a5,bB.x); fma2(acc[5][3],a5,bB.y);
            fma2(acc[6][0],a6,bA.x); fma2(acc[6][1],a6,bA.y); fma2(acc[6][2],a6,bB.x); fma2(acc[6][3],a6,bB.y);
            fma2(acc[7][0],a7,bA.x); fma2(acc[7][1],a7,bA.y); fma2(acc[7][2],a7,bB.x); fma2(acc[7][3],a7,bB.y);
        }
    }

    float* dst = (dir? g_no : g_ni) + (size_t)b*SL*ND + (size_t)mtile*64*ND;
#pragma unroll
    for (int i=0;i<8;++i){
        float* drow = dst + (size_t)(rg*8+i)*ND;
        float v0,v1,v2,v3;
        upk2(acc[i][0],v0,v1); upk2(acc[i][1],v2,v3);
        *(float4*)(drow+cA) = make_float4(v0,v1,v2,v3);
        upk2(acc[i][2],v0,v1); upk2(acc[i][3],v2,v3);
        *(float4*)(drow+cB) = make_float4(v0,v1,v2,v3);
    }
}

// ---- kernel 3: fused GRU update (verified; untouched) ----
__global__ void __launch_bounds__(256) gru_kernel(
    const float* __restrict__ x,
    const float* __restrict__ W_r, const float* __restrict__ b_r,
    const float* __restrict__ W_z, const float* __restrict__ b_z,
    const float* __restrict__ W_h, const float* __restrict__ b_h,
    float* __restrict__ dout, int use_x, int is_final)
{
    __shared__ GSmem s;
    const int stile=blockIdx.x, b=blockIdx.z;
    const size_t base=(size_t)b*SL*ND + (size_t)stile*64*ND;
    const float* ni=g_ni+base; const float* no=g_no+base;
    const float* st=(use_x? x : (const float*)g_st)+base;
    const int tid=threadIdx.x, r0=(tid>>4)*4, c0=(tid&15)*8;

    u64 acc[4][4];
    ZERO_ACC(acc);
    gemm64<24,true>(ni,no,st,ND,W_r,acc,s.g);

    float stv[4][8];
#pragma unroll
    for (int i=0;i<4;++i){
        float4 p0=*(const float4*)(st+(size_t)(r0+i)*ND+c0);
        float4 p1=*(const float4*)(st+(size_t)(r0+i)*ND+c0+4);
        stv[i][0]=p0.x; stv[i][1]=p0.y; stv[i][2]=p0.z; stv[i][3]=p0.w;
        stv[i][4]=p1.x; stv[i][5]=p1.y; stv[i][6]=p1.z; stv[i][7]=p1.w;
    }
#pragma unroll
    for (int i=0;i<4;++i)
#pragma unroll
        for (int j=0;j<4;++j){
            float v0,v1; upk2(acc[i][j],v0,v1);
            const int c=c0+2*j;
            s.ro[r0+i][c]   = sigm(v0+b_r[c])  *stv[i][2*j];
            s.ro[r0+i][c+1] = sigm(v1+b_r[c+1])*stv[i][2*j+1];
        }
    __syncthreads();

    ZERO_ACC(acc);
    gemm64<24,true>(ni,no,st,ND,W_z,acc,s.g);
    float zv[4][8];
#pragma unroll
    for (int i=0;i<4;++i)
#pragma unroll
        for (int j=0;j<4;++j){
            float v0,v1; upk2(acc[i][j],v0,v1);
            zv[i][2*j]  =sigm(v0+b_z[c0+2*j]);
            zv[i][2*j+1]=sigm(v1+b_z[c0+2*j+1]);
        }

    ZERO_ACC(acc);
    gemm64<24,true>(ni,no,(const float*)s.ro,ND,W_h,acc,s.g);

    float* ost = g_st + base;
    float* od  = dout + base;
#pragma unroll
    for (int i=0;i<4;++i){
        float o[8];
#pragma unroll
        for (int j=0;j<4;++j){
            float v0,v1; upk2(acc[i][j],v0,v1);
            float h0=tanhf(v0+b_h[c0+2*j]), h1=tanhf(v1+b_h[c0+2*j+1]);
            o[2*j]  =(1.f-zv[i][2*j])  *stv[i][2*j]  + zv[i][2*j]  *h0;
            o[2*j+1]=(1.f-zv[i][2*j+1])*stv[i][2*j+1] + zv[i][2*j+1]*h1;
        }
        *(float4*)(ost+(size_t)(r0+i)*ND+c0)   = make_float4(o[0],o[1],o[2],o[3]);
        *(float4*)(ost+(size_t)(r0+i)*ND+c0+4) = make_float4(o[4],o[5],o[6],o[7]);
        if (is_final){
            *(float4*)(od+(size_t)(r0+i)*ND+c0)   = make_float4(o[0],o[1],o[2],o[3]);
            *(float4*)(od+(size_t)(r0+i)*ND+c0+4) = make_float4(o[4],o[5],o[6],o[7]);
        }
    }
}

extern "C" void kernel_launch(void* const* d_in, const int* in_sizes, int n_in,
                              void* d_out, int out_size)
{
    const float* x      = (const float*)d_in[0];
    const float* A_in   = (const float*)d_in[1];
    const float* A_out  = (const float*)d_in[2];
    const float* W_ein  = (const float*)d_in[3];
    const float* b_ein  = (const float*)d_in[4];
    const float* W_eout = (const float*)d_in[5];
    const float* b_eout = (const float*)d_in[6];
    const float* W_r    = (const float*)d_in[7];
    const float* b_r    = (const float*)d_in[8];
    const float* W_z    = (const float*)d_in[9];
    const float* b_z    = (const float*)d_in[10];
    const float* W_h    = (const float*)d_in[11];
    const float* b_h    = (const float*)d_in[12];
    float* out = (float*)d_out;

    for (int step=0; step<5; ++step){
        const int use_x = (step==0), fin = (step==4);
        proj_kernel<<<dim3(16,8,4),256>>>(x, W_ein,b_ein,W_eout,b_eout, use_x);
        agg_kernel <<<dim3(16,2,4),128>>>(A_in, A_out);
        gru_kernel <<<dim3(16,1,4),256>>>(x, W_r,b_r,W_z,b_z,W_h,b_h, out, use_x, fin);
    }
}

// round 12
// speedup vs baseline: 1.7144x; 1.1430x over previous
#include <cuda_runtime.h>
#include <cuda_bf16.h>

#define SL 1024
#define NE 4
#define ND 128
#define NBATCH 4
#define KA (SL*NE)

typedef unsigned long long u64;
typedef unsigned int u32;

// ---- scratch (no allocs allowed) ----
__device__ __align__(128) float g_pi[(size_t)NBATCH*KA*ND];
__device__ __align__(128) float g_po[(size_t)NBATCH*KA*ND];
__device__ __align__(128) float g_ni[(size_t)NBATCH*SL*ND];
__device__ __align__(128) float g_no[(size_t)NBATCH*SL*ND];
__device__ __align__(128) float g_st[(size_t)NBATCH*SL*ND];

// ---- packed f32x2 helpers ----
__device__ __forceinline__ u64 pk2(float a, float b){
    u64 r; asm("mov.b64 %0,{%1,%2};":"=l"(r):"r"(__float_as_uint(a)),"r"(__float_as_uint(b))); return r;
}
__device__ __forceinline__ void upk2(u64 v, float&a, float&b){
    u32 lo,hi; asm("mov.b64 {%0,%1},%2;":"=r"(lo),"=r"(hi):"l"(v));
    a=__uint_as_float(lo); b=__uint_as_float(hi);
}
__device__ __forceinline__ void fma2(u64&d, u64 a, u64 b){
    asm("fma.rn.f32x2 %0,%1,%2,%0;":"+l"(d):"l"(a),"l"(b));
}
__device__ __forceinline__ float sigm(float v){ return 1.f/(1.f+__expf(-v)); }

__device__ __forceinline__ u32 smem_u32(const void* p){
    u32 a; asm("{ .reg .u64 t; cvta.to.shared.u64 t,%1; cvt.u32.u64 %0,t; }":"=r"(a):"l"(p));
    return a;
}
__device__ __forceinline__ void cpa16(u32 dst, const void* src){
    asm volatile("cp.async.cg.shared.global [%0],[%1],16;"::"r"(dst),"l"(src));
}
__device__ __forceinline__ void cpa_commit(){ asm volatile("cp.async.commit_group;"); }
__device__ __forceinline__ void cpa_wait0(){ asm volatile("cp.async.wait_group 0;"); }
__device__ __forceinline__ void cpa_wait1(){ asm volatile("cp.async.wait_group 1;"); }
__device__ __forceinline__ void cpa_wait2(){ asm volatile("cp.async.wait_group 2;"); }

struct Smem { u64 A2[16][64]; float Bs[16][128]; };          // 16 KB  (proj, 256 thr)
struct Smem32 { u64 A2[16][32]; float Bs[16][128]; };        // 12 KB  (gru, 128 thr)
struct GSmem32 { Smem32 g; float ro[32][ND]; };              // 28 KB

// ---- verified 64-row FFMA2 GEMM core (proj; 256 threads; untouched) ----
template<int NT, bool SEG3>
__device__ __forceinline__ void gemm64(
    const float* a0, const float* a1, const float* a2, int lda,
    const float* __restrict__ Bmat, u64 (&acc)[4][4], Smem& sm)
{
    const int tid=threadIdx.x;
    const int r0=(tid>>4)*4, c0=(tid&15)*8;
    const int arow=tid>>2, ac=(tid&3)*4;
    const int bw=tid>>5, bc=(tid&31)*4;
    float4 ra,rb0,rb1;
    ra  = *(const float4*)(a0 + (size_t)arow*lda + ac);
    rb0 = *(const float4*)(Bmat + bw*ND + bc);
    rb1 = *(const float4*)(Bmat + (bw+8)*ND + bc);
#pragma unroll 1
    for (int kt=0; kt<NT; ++kt){
        sm.A2[ac+0][arow]=pk2(ra.x,ra.x); sm.A2[ac+1][arow]=pk2(ra.y,ra.y);
        sm.A2[ac+2][arow]=pk2(ra.z,ra.z); sm.A2[ac+3][arow]=pk2(ra.w,ra.w);
        *(float4*)&sm.Bs[bw][bc]=rb0; *(float4*)&sm.Bs[bw+8][bc]=rb1;
        __syncthreads();
        if (kt+1<NT){
            const int kn=kt+1; const float* ap; int off;
            if (SEG3){ ap=(kn<8)?a0:((kn<16)?a1:a2); off=(kn&7)*16; }
            else     { ap=a0; off=kn*16; }
            ra = *(const float4*)(ap + (size_t)arow*lda + off + ac);
            const float* bp = Bmat + (size_t)kn*16*ND;
            rb0 = *(const float4*)(bp + bw*ND + bc);
            rb1 = *(const float4*)(bp + (bw+8)*ND + bc);
        }
#pragma unroll
        for (int kk=0;kk<16;++kk){
            u64 a0v=sm.A2[kk][r0],a1v=sm.A2[kk][r0+1],a2v=sm.A2[kk][r0+2],a3v=sm.A2[kk][r0+3];
            ulonglong2 b01=*(const ulonglong2*)&sm.Bs[kk][c0];
            ulonglong2 b23=*(const ulonglong2*)&sm.Bs[kk][c0+4];
            fma2(acc[0][0],a0v,b01.x); fma2(acc[0][1],a0v,b01.y); fma2(acc[0][2],a0v,b23.x); fma2(acc[0][3],a0v,b23.y);
            fma2(acc[1][0],a1v,b01.x); fma2(acc[1][1],a1v,b01.y); fma2(acc[1][2],a1v,b23.x); fma2(acc[1][3],a1v,b23.y);
            fma2(acc[2][0],a2v,b01.x); fma2(acc[2][1],a2v,b01.y); fma2(acc[2][2],a2v,b23.x); fma2(acc[2][3],a2v,b23.y);
            fma2(acc[3][0],a3v,b01.x); fma2(acc[3][1],a3v,b01.y); fma2(acc[3][2],a3v,b23.x); fma2(acc[3][3],a3v,b23.y);
        }
        __syncthreads();
    }
}

// ---- 32-row variant (gru; 128 threads). Same staging pattern & k order. ----
template<int NT>
__device__ __forceinline__ void gemm32(
    const float* a0, const float* a1, const float* a2,
    const float* __restrict__ Bmat, u64 (&acc)[4][4], Smem32& sm)
{
    const int tid=threadIdx.x;
    const int r0=(tid>>4)*4, c0=(tid&15)*8;      // 8 row-groups x 4 = 32 rows; 16 col-groups x 8
    const int arow=tid>>2, ac=(tid&3)*4;         // 32 rows x 16 k
    const int bw=tid>>5, bc=(tid&31)*4;          // B rows bw, bw+4, bw+8, bw+12
    float4 ra,rb0,rb1,rb2,rb3;
    ra  = *(const float4*)(a0 + (size_t)arow*ND + ac);
    rb0 = *(const float4*)(Bmat + bw*ND + bc);
    rb1 = *(const float4*)(Bmat + (bw+4)*ND + bc);
    rb2 = *(const float4*)(Bmat + (bw+8)*ND + bc);
    rb3 = *(const float4*)(Bmat + (bw+12)*ND + bc);
#pragma unroll 1
    for (int kt=0; kt<NT; ++kt){
        sm.A2[ac+0][arow]=pk2(ra.x,ra.x); sm.A2[ac+1][arow]=pk2(ra.y,ra.y);
        sm.A2[ac+2][arow]=pk2(ra.z,ra.z); sm.A2[ac+3][arow]=pk2(ra.w,ra.w);
        *(float4*)&sm.Bs[bw][bc]   =rb0;
        *(float4*)&sm.Bs[bw+4][bc] =rb1;
        *(float4*)&sm.Bs[bw+8][bc] =rb2;
        *(float4*)&sm.Bs[bw+12][bc]=rb3;
        __syncthreads();
        if (kt+1<NT){
            const int kn=kt+1;
            const float* ap=(kn<8)?a0:((kn<16)?a1:a2);
            const int off=(kn&7)*16;
            ra = *(const float4*)(ap + (size_t)arow*ND + off + ac);
            const float* bp = Bmat + (size_t)kn*16*ND;
            rb0 = *(const float4*)(bp + bw*ND + bc);
            rb1 = *(const float4*)(bp + (bw+4)*ND + bc);
            rb2 = *(const float4*)(bp + (bw+8)*ND + bc);
            rb3 = *(const float4*)(bp + (bw+12)*ND + bc);
        }
#pragma unroll
        for (int kk=0;kk<16;++kk){
            u64 a0v=sm.A2[kk][r0],a1v=sm.A2[kk][r0+1],a2v=sm.A2[kk][r0+2],a3v=sm.A2[kk][r0+3];
            ulonglong2 b01=*(const ulonglong2*)&sm.Bs[kk][c0];
            ulonglong2 b23=*(const ulonglong2*)&sm.Bs[kk][c0+4];
            fma2(acc[0][0],a0v,b01.x); fma2(acc[0][1],a0v,b01.y); fma2(acc[0][2],a0v,b23.x); fma2(acc[0][3],a0v,b23.y);
            fma2(acc[1][0],a1v,b01.x); fma2(acc[1][1],a1v,b01.y); fma2(acc[1][2],a1v,b23.x); fma2(acc[1][3],a1v,b23.y);
            fma2(acc[2][0],a2v,b01.x); fma2(acc[2][1],a2v,b01.y); fma2(acc[2][2],a2v,b23.x); fma2(acc[2][3],a2v,b23.y);
            fma2(acc[3][0],a3v,b01.x); fma2(acc[3][1],a3v,b01.y); fma2(acc[3][2],a3v,b23.x); fma2(acc[3][3],a3v,b23.y);
        }
        __syncthreads();
    }
}
#define ZERO_ACC(acc) { _Pragma("unroll") for(int i=0;i<4;++i){ _Pragma("unroll") for(int j=0;j<4;++j) acc[i][j]=0ull; } }

// ---- kernel 1: per-edge projections (verified; untouched) ----
__global__ void __launch_bounds__(256) proj_kernel(
    const float* __restrict__ x,
    const float* __restrict__ W_ein, const float* __restrict__ b_ein,
    const float* __restrict__ W_eout, const float* __restrict__ b_eout, int use_x)
{
    __shared__ Smem sm;
    const int stile=blockIdx.x, e=blockIdx.y>>1, dir=blockIdx.y&1, b=blockIdx.z;
    const float* src = (use_x? x : (const float*)g_st) + (size_t)b*SL*ND + (size_t)stile*64*ND;
    const float* W   = (dir? W_eout : W_ein) + (size_t)e*ND*ND;
    const float* bias= (dir? b_eout : b_ein) + e*ND;
    float* dst = (dir? g_po : g_pi) + (size_t)b*KA*ND;

    u64 acc[4][4]; ZERO_ACC(acc);
    gemm64<8,false>(src, src, src, ND, W, acc, sm);

    const int tid=threadIdx.x, r0=(tid>>4)*4, c0=(tid&15)*8;
#pragma unroll
    for (int i=0;i<4;++i){
        const int s = stile*64 + r0 + i;
        float* drow = dst + ((size_t)s*NE + e)*ND;
        float v0,v1,v2,v3;
        upk2(acc[i][0],v0,v1); upk2(acc[i][1],v2,v3);
        *(float4*)(drow+c0)   = make_float4(v0+bias[c0],v1+bias[c0+1],v2+bias[c0+2],v3+bias[c0+3]);
        upk2(acc[i][2],v0,v1); upk2(acc[i][3],v2,v3);
        *(float4*)(drow+c0+4) = make_float4(v0+bias[c0+4],v1+bias[c0+5],v2+bias[c0+6],v3+bias[c0+7]);
    }
}

// ---- kernel 2: fp32 aggregation — 8x8 microtile (verified round 11; untouched) ----
__global__ void __launch_bounds__(128,2) agg_kernel(
    const float* __restrict__ A_in, const float* __restrict__ A_out)
{
    __shared__ __align__(16) float Bs[4][16][128];
    __shared__ __align__(16) float As[2][16][64];

    const int tid=threadIdx.x;
    const int mtile=blockIdx.x, dir=blockIdx.y, b=blockIdx.z;
    const float* Arow = (dir? A_out : A_in) + (size_t)b*SL*KA + (size_t)mtile*64*KA;
    const float* Prow = (dir? g_po : g_pi) + (size_t)b*KA*ND;

    const u32 bbase = smem_u32(&Bs[0][0][0]);
    auto issueB = [&](int t){
        const u32 slot = bbase + (u32)(t&3)*8192;
#pragma unroll
        for (int j=0;j<4;++j){
            const int id=tid+j*128, r=id>>5, c=id&31;
            cpa16(slot + r*512 + c*16, Prow + (size_t)(t*16+r)*ND + c*4);
        }
        cpa_commit();
    };

    const int ar = tid&63, akc = (tid>>6)*8;
    auto stsA = [&](int buf, const float4& p0, const float4& p1){
        As[buf][akc+0][ar]=p0.x; As[buf][akc+1][ar]=p0.y;
        As[buf][akc+2][ar]=p0.z; As[buf][akc+3][ar]=p0.w;
        As[buf][akc+4][ar]=p1.x; As[buf][akc+5][ar]=p1.y;
        As[buf][akc+6][ar]=p1.z; As[buf][akc+7][ar]=p1.w;
    };

    float4 ra0 = *(const float4*)(Arow + (size_t)ar*KA + akc);
    float4 ra1 = *(const float4*)(Arow + (size_t)ar*KA + akc + 4);
    issueB(0); issueB(1); issueB(2);
    stsA(0, ra0, ra1);
    ra0 = *(const float4*)(Arow + (size_t)ar*KA + 16 + akc);
    ra1 = *(const float4*)(Arow + (size_t)ar*KA + 16 + akc + 4);

    const int rg = tid>>4;
    const int cA = (tid&15)*4, cB = 64 + cA;
    u64 acc[8][4];
#pragma unroll
    for (int i=0;i<8;++i)
#pragma unroll
        for (int j=0;j<4;++j) acc[i][j]=0ull;

#pragma unroll 1
    for (int t=0; t<256; ++t){
        if (t<254) cpa_wait2(); else if (t==254) cpa_wait1(); else cpa_wait0();
        __syncthreads();
        if (t+3<256) issueB(t+3);
        if (t+1<256) stsA((t+1)&1, ra0, ra1);
        if (t+2<256){
            ra0 = *(const float4*)(Arow + (size_t)ar*KA + (t+2)*16 + akc);
            ra1 = *(const float4*)(Arow + (size_t)ar*KA + (t+2)*16 + akc + 4);
        }
        const int ab=t&1, bs=t&3;
#pragma unroll
        for (int kk=0;kk<16;++kk){
            float4 pa0 = *(const float4*)&As[ab][kk][rg*8];
            float4 pa1 = *(const float4*)&As[ab][kk][rg*8+4];
            ulonglong2 bA = *(const ulonglong2*)&Bs[bs][kk][cA];
            ulonglong2 bB = *(const ulonglong2*)&Bs[bs][kk][cB];
            u64 a0=pk2(pa0.x,pa0.x), a1=pk2(pa0.y,pa0.y), a2=pk2(pa0.z,pa0.z), a3=pk2(pa0.w,pa0.w);
            u64 a4=pk2(pa1.x,pa1.x), a5=pk2(pa1.y,pa1.y), a6=pk2(pa1.z,pa1.z), a7=pk2(pa1.w,pa1.w);
            fma2(acc[0][0],a0,bA.x); fma2(acc[0][1],a0,bA.y); fma2(acc[0][2],a0,bB.x); fma2(acc[0][3],a0,bB.y);
            fma2(acc[1][0],a1,bA.x); fma2(acc[1][1],a1,bA.y); fma2(acc[1][2],a1,bB.x); fma2(acc[1][3],a1,bB.y);
            fma2(acc[2][0],a2,bA.x); fma2(acc[2][1],a2,bA.y); fma2(acc[2][2],a2,bB.x); fma2(acc[2][3],a2,bB.y);
            fma2(acc[3][0],a3,bA.x); fma2(acc[3][1],a3,bA.y); fma2(acc[3][2],a3,bB.x); fma2(acc[3][3],a3,bB.y);
            fma2(acc[4][0],a4,bA.x); fma2(acc[4][1],a4,bA.y); fma2(acc[4][2],a4,bB.x); fma2(acc[4][3],a4,bB.y);
            fma2(acc[5][0],a5,bA.x); fma2(acc[5][1],a5,bA.y); fma2(acc[5][2],a5,bB.x); fma2(acc[5][3],a5,bB.y);
            fma2(acc[6][0],a6,bA.x); fma2(acc[6][1],a6,bA.y); fma2(acc[6][2],a6,bB.x); fma2(acc[6][3],a6,bB.y);
            fma2(acc[7][0],a7,bA.x); fma2(acc[7][1],a7,bA.y); fma2(acc[7][2],a7,bB.x); fma2(acc[7][3],a7,bB.y);
        }
    }

    float* dst = (dir? g_no : g_ni) + (size_t)b*SL*ND + (size_t)mtile*64*ND;
#pragma unroll
    for (int i=0;i<8;++i){
        float* drow = dst + (size_t)(rg*8+i)*ND;
        float v0,v1,v2,v3;
        upk2(acc[i][0],v0,v1); upk2(acc[i][1],v2,v3);
        *(float4*)(drow+cA) = make_float4(v0,v1,v2,v3);
        upk2(acc[i][2],v0,v1); upk2(acc[i][3],v2,v3);
        *(float4*)(drow+cB) = make_float4(v0,v1,v2,v3);
    }
}

// ---- kernel 3: fused GRU update — 32-row tiles, 128 CTAs ----
__global__ void __launch_bounds__(128) gru_kernel(
    const float* __restrict__ x,
    const float* __restrict__ W_r, const float* __restrict__ b_r,
    const float* __restrict__ W_z, const float* __restrict__ b_z,
    const float* __restrict__ W_h, const float* __restrict__ b_h,
    float* __restrict__ dout, int use_x, int is_final)
{
    __shared__ GSmem32 s;
    const int stile=blockIdx.x, b=blockIdx.z;
    const size_t base=(size_t)b*SL*ND + (size_t)stile*32*ND;
    const float* ni=g_ni+base; const float* no=g_no+base;
    const float* st=(use_x? x : (const float*)g_st)+base;
    const int tid=threadIdx.x, r0=(tid>>4)*4, c0=(tid&15)*8;

    u64 acc[4][4];
    ZERO_ACC(acc);
    gemm32<24>(ni,no,st,W_r,acc,s.g);

    float stv[4][8];
#pragma unroll
    for (int i=0;i<4;++i){
        float4 p0=*(const float4*)(st+(size_t)(r0+i)*ND+c0);
        float4 p1=*(const float4*)(st+(size_t)(r0+i)*ND+c0+4);
        stv[i][0]=p0.x; stv[i][1]=p0.y; stv[i][2]=p0.z; stv[i][3]=p0.w;
        stv[i][4]=p1.x; stv[i][5]=p1.y; stv[i][6]=p1.z; stv[i][7]=p1.w;
    }
#pragma unroll
    for (int i=0;i<4;++i)
#pragma unroll
        for (int j=0;j<4;++j){
            float v0,v1; upk2(acc[i][j],v0,v1);
            const int c=c0+2*j;
            s.ro[r0+i][c]   = sigm(v0+b_r[c])  *stv[i][2*j];
            s.ro[r0+i][c+1] = sigm(v1+b_r[c+1])*stv[i][2*j+1];
        }
    __syncthreads();

    ZERO_ACC(acc);
    gemm32<24>(ni,no,st,W_z,acc,s.g);
    float zv[4][8];
#pragma unroll
    for (int i=0;i<4;++i)
#pragma unroll
        for (int j=0;j<4;++j){
            float v0,v1; upk2(acc[i][j],v0,v1);
            zv[i][2*j]  =sigm(v0+b_z[c0+2*j]);
            zv[i][2*j+1]=sigm(v1+b_z[c0+2*j+1]);
        }

    ZERO_ACC(acc);
    gemm32<24>(ni,no,(const float*)s.ro,W_h,acc,s.g);

    float* ost = g_st + base;
    float* od  = dout + base;
#pragma unroll
    for (int i=0;i<4;++i){
        float o[8];
#pragma unroll
        for (int j=0;j<4;++j){
            float v0,v1; upk2(acc[i][j],v0,v1);
            float h0=tanhf(v0+b_h[c0+2*j]), h1=tanhf(v1+b_h[c0+2*j+1]);
            o[2*j]  =(1.f-zv[i][2*j])  *stv[i][2*j]  + zv[i][2*j]  *h0;
            o[2*j+1]=(1.f-zv[i][2*j+1])*stv[i][2*j+1] + zv[i][2*j+1]*h1;
        }
        *(float4*)(ost+(size_t)(r0+i)*ND+c0)   = make_float4(o[0],o[1],o[2],o[3]);
        *(float4*)(ost+(size_t)(r0+i)*ND+c0+4) = make_float4(o[4],o[5],o[6],o[7]);
        if (is_final){
            *(float4*)(od+(size_t)(r0+i)*ND+c0)   = make_float4(o[0],o[1],o[2],o[3]);
            *(float4*)(od+(size_t)(r0+i)*ND+c0+4) = make_float4(o[4],o[5],o[6],o[7]);
        }
    }
}

extern "C" void kernel_launch(void* const* d_in, const int* in_sizes, int n_in,
                              void* d_out, int out_size)
{
    const float* x      = (const float*)d_in[0];
    const float* A_in   = (const float*)d_in[1];
    const float* A_out  = (const float*)d_in[2];
    const float* W_ein  = (const float*)d_in[3];
    const float* b_ein  = (const float*)d_in[4];
    const float* W_eout = (const float*)d_in[5];
    const float* b_eout = (const float*)d_in[6];
    const float* W_r    = (const float*)d_in[7];
    const float* b_r    = (const float*)d_in[8];
    const float* W_z    = (const float*)d_in[9];
    const float* b_z    = (const float*)d_in[10];
    const float* W_h    = (const float*)d_in[11];
    const float* b_h    = (const float*)d_in[12];
    float* out = (float*)d_out;

    for (int step=0; step<5; ++step){
        const int use_x = (step==0), fin = (step==4);
        proj_kernel<<<dim3(16,8,4),256>>>(x, W_ein,b_ein,W_eout,b_eout, use_x);
        agg_kernel <<<dim3(16,2,4),128>>>(A_in, A_out);
        gru_kernel <<<dim3(32,1,4),128>>>(x, W_r,b_r,W_z,b_z,W_h,b_h, out, use_x, fin);
    }
}